// round 2
// baseline (speedup 1.0000x reference)
#include <cuda_runtime.h>

#define CUT2 25.0f

// Scratch: per-row (s*nat+i) pair counts and exclusive offsets.
__device__ int g_counts[131072];
__device__ int g_offsets[131072];
__device__ int g_npairs;

// sq = ((x*x + y*y) + z*z) with all-RN ops (XLA elementwise mul + reduce-add:
// no contraction).
__device__ __forceinline__ float sqnorm3(float x, float y, float z) {
    return __fadd_rn(__fadd_rn(__fmul_rn(x, x), __fmul_rn(y, y)), __fmul_rn(z, z));
}
// gram dot via GEMM-style FMA chain (cublas SIMT / Eigen k-loop):
//   c = rn(x*x'); c = fma(y,y',c); c = fma(z,z',c)
__device__ __forceinline__ float dot3(float4 a, float4 b) {
    return __fmaf_rn(a.z, b.z, __fmaf_rn(a.y, b.y, __fmul_rn(a.x, b.x)));
}
// d12 = (sq_i + sq_j) - 2*gram, all RN (2*gram is exact).
__device__ __forceinline__ float d12_of(float4 ai, float4 aj) {
    return __fsub_rn(__fadd_rn(ai.w, aj.w), __fmul_rn(2.0f, dot3(ai, aj)));
}

extern __shared__ float4 s_at[];  // nat entries: (x, y, z, sq)

__device__ __forceinline__ void load_system_smem(const float* __restrict__ coords,
                                                 int s, int nat) {
    const float* base = coords + (size_t)s * nat * 3;
    for (int t = threadIdx.x; t < nat; t += blockDim.x) {
        float x = base[3 * t + 0];
        float y = base[3 * t + 1];
        float z = base[3 * t + 2];
        s_at[t] = make_float4(x, y, z, sqnorm3(x, y, z));
    }
    __syncthreads();
}

// K1: per-row half-list neighbor counts. grid = (nsys, CHUNKS), block = 256.
__global__ void count_kernel(const float* __restrict__ coords, int nat) {
    int s = blockIdx.x;
    load_system_smem(coords, s, nat);

    int lane = threadIdx.x & 31;
    int wid  = (threadIdx.x >> 5) + blockIdx.y * (blockDim.x >> 5);
    int wtot = (blockDim.x >> 5) * gridDim.y;

    for (int i = wid; i < nat; i += wtot) {
        float4 ai = s_at[i];
        int cnt = 0;
        for (int j = i + 1 + lane; j < nat; j += 32) {
            float d12 = d12_of(ai, s_at[j]);
            cnt += (d12 < CUT2) ? 1 : 0;
        }
#pragma unroll
        for (int o = 16; o; o >>= 1) cnt += __shfl_down_sync(0xffffffffu, cnt, o);
        if (lane == 0) g_counts[s * nat + i] = cnt;
    }
}

// K2: exclusive prefix scan over nrows counts (single 1024-thread block).
__global__ void scan_kernel(int nrows) {
    __shared__ int sh[1024];
    int tid = threadIdx.x;
    int per = (nrows + 1023) >> 10;
    int start = tid * per;
    int end = start + per;
    if (end > nrows) end = nrows;

    int s = 0;
    for (int k = start; k < end; k++) s += g_counts[k];
    sh[tid] = s;
    __syncthreads();

#pragma unroll
    for (int off = 1; off < 1024; off <<= 1) {
        int v = (tid >= off) ? sh[tid - off] : 0;
        __syncthreads();
        sh[tid] += v;
        __syncthreads();
    }

    int run = sh[tid] - s;  // exclusive prefix of this segment
    for (int k = start; k < end; k++) {
        g_offsets[k] = run;
        run += g_counts[k];
    }
    if (tid == 1023) g_npairs = sh[1023];
}

// K3: ordered compaction write. Output float32 layout (maxp = MAX_PAIRS):
//   [0,M): src   [M,2M): dst    (edge_src = concat(src,dst))
//   [2M,3M): dst [3M,4M): src   (edge_dst = concat(dst,src))
//   [4M,5M): d12 [5M,6M): d12
//   [6M]: npairs
__global__ void fill_kernel(const float* __restrict__ coords, int nat,
                            float* __restrict__ out, int maxp) {
    int s = blockIdx.x;
    load_system_smem(coords, s, nat);

    int lane = threadIdx.x & 31;
    int wid  = (threadIdx.x >> 5) + blockIdx.y * (blockDim.x >> 5);
    int wtot = (blockDim.x >> 5) * gridDim.y;

    for (int i = wid; i < nat; i += wtot) {
        float4 ai = s_at[i];
        int off = g_offsets[s * nat + i];
        float fsrc = (float)(s * nat + i);
        int written = 0;
        for (int j0 = i + 1; j0 < nat; j0 += 32) {
            int j = j0 + lane;
            float d12 = CUT2;
            bool hit = false;
            if (j < nat) {
                d12 = d12_of(ai, s_at[j]);
                hit = (d12 < CUT2);
            }
            unsigned m = __ballot_sync(0xffffffffu, hit);
            if (hit) {
                int pos = off + written + __popc(m & ((1u << lane) - 1u));
                if (pos < maxp) {
                    float fdst = (float)(s * nat + j);
                    out[pos]            = fsrc;
                    out[maxp + pos]     = fdst;
                    out[2 * maxp + pos] = fdst;
                    out[3 * maxp + pos] = fsrc;
                    out[4 * maxp + pos] = d12;
                    out[5 * maxp + pos] = d12;
                }
            }
            written += __popc(m);
        }
    }
}

// K4: padding entries (k >= npairs): src/dst = padding_value (= n atoms),
// d12 = cutoff^2. Also writes the npairs scalar at out[6*maxp].
__global__ void pad_kernel(float* __restrict__ out, int maxp, float padval) {
    int k = blockIdx.x * blockDim.x + threadIdx.x;
    int np = g_npairs;
    if (k == 0) out[6 * maxp] = (float)np;
    if (k < maxp && k >= np) {
        out[k]            = padval;
        out[maxp + k]     = padval;
        out[2 * maxp + k] = padval;
        out[3 * maxp + k] = padval;
        out[4 * maxp + k] = CUT2;
        out[5 * maxp + k] = CUT2;
    }
}

extern "C" void kernel_launch(void* const* d_in, const int* in_sizes, int n_in,
                              void* d_out, int out_size) {
    const float* coords = (const float*)d_in[0];
    int n    = in_sizes[1];          // total atoms (isys length)
    int nsys = in_sizes[2];          // natoms length
    int nat  = n / nsys;
    int maxp = (out_size - 1) / 6;   // MAX_PAIRS from output buffer size
    float* out = (float*)d_out;

    size_t smem = (size_t)nat * sizeof(float4);
    dim3 grid(nsys, 4);

    count_kernel<<<grid, 256, smem>>>(coords, nat);
    scan_kernel<<<1, 1024>>>(n);
    fill_kernel<<<grid, 256, smem>>>(coords, nat, out, maxp);
    pad_kernel<<<(maxp + 255) / 256, 256>>>(out, maxp, (float)n);
}

// round 3
// speedup vs baseline: 1.5728x; 1.5728x over previous
#include <cuda_runtime.h>

#define CUT2 25.0f
#define IT 4          // i-rows per warp iteration (register tile)
#define SLOTS 128     // per-row stash capacity (mean ~26 hits, Poisson tail << 128)
#define NROWS_CAP 65536

// Scratch (static __device__, allocation-free).
__device__ int    g_counts[NROWS_CAP];
__device__ int    g_offsets[NROWS_CAP];
__device__ int    g_npairs;
__device__ float2 g_pair[NROWS_CAP * SLOTS];   // {fdst_global, d12} per hit, j-ordered

// ---- bit-exact reference arithmetic (DO NOT CHANGE) ----
// sq = ((x*x + y*y) + z*z), all-RN (XLA elementwise + reduce: no contraction)
__device__ __forceinline__ float sqnorm3(float x, float y, float z) {
    return __fadd_rn(__fadd_rn(__fmul_rn(x, x), __fmul_rn(y, y)), __fmul_rn(z, z));
}
// gram dot via GEMM-style FMA chain: c = rn(x*x'); c = fma(y,y',c); c = fma(z,z',c)
__device__ __forceinline__ float dot3(float4 a, float4 b) {
    return __fmaf_rn(a.z, b.z, __fmaf_rn(a.y, b.y, __fmul_rn(a.x, b.x)));
}
// d12 = (sq_i + sq_j) - 2*gram, all RN
__device__ __forceinline__ float d12_of(float4 ai, float4 aj) {
    return __fsub_rn(__fadd_rn(ai.w, aj.w), __fmul_rn(2.0f, dot3(ai, aj)));
}
// --------------------------------------------------------

extern __shared__ float4 s_at[];  // nat entries: (x, y, z, sq)

__device__ __forceinline__ void load_system_smem(const float* __restrict__ coords,
                                                 int s, int nat) {
    const float* base = coords + (size_t)s * nat * 3;
    for (int t = threadIdx.x; t < nat; t += blockDim.x) {
        float x = base[3 * t + 0];
        float y = base[3 * t + 1];
        float z = base[3 * t + 2];
        s_at[t] = make_float4(x, y, z, sqnorm3(x, y, z));
    }
    __syncthreads();
}

// K1: single sweep. Each warp processes IT consecutive rows at once; lanes
// stride j. Hits are stashed per-row in j-order (ballot rank), counts written.
// grid = (nsys, G), block = 256.
__global__ void sweep_kernel(const float* __restrict__ coords, int nat) {
    int s = blockIdx.x;
    load_system_smem(coords, s, nat);

    int lane = threadIdx.x & 31;
    int wid  = (threadIdx.x >> 5) + blockIdx.y * (blockDim.x >> 5);
    int wtot = (blockDim.x >> 5) * gridDim.y;
    int ngroups = (nat + IT - 1) / IT;
    float fsysbase = (float)(s * nat);

    for (int g = wid; g < ngroups; g += wtot) {
        int r0 = g * IT;
        float4 a[IT];
        int written[IT];
#pragma unroll
        for (int t = 0; t < IT; t++) {
            int i = r0 + t;
            a[t] = (i < nat) ? s_at[i] : make_float4(0.f, 0.f, 0.f, 1e30f);
            written[t] = 0;
        }

        // Diagonal mini-block: j in (i, r0+IT). These are the smallest j for
        // each row, written first to preserve j-ascending order.
#pragma unroll
        for (int t = 0; t < IT; t++) {
            int i = r0 + t;
            int j = i + 1 + lane;
            float d = 0.f;
            bool hit = false;
            if (j < r0 + IT && j < nat) {
                d = d12_of(a[t], s_at[j]);
                hit = (d < CUT2);
            }
            unsigned m = __ballot_sync(0xffffffffu, hit);
            if (hit) {
                int slot = __popc(m & ((1u << lane) - 1u));
                g_pair[(s * nat + i) * SLOTS + slot] =
                    make_float2(fsysbase + (float)j, d);
            }
            written[t] = __popc(m);
        }

        // Main sweep: j from r0+IT; one smem load serves IT rows.
        for (int j0 = r0 + IT; j0 < nat; j0 += 32) {
            int j = j0 + lane;
            bool valid = (j < nat);
            float4 aj = valid ? s_at[j] : make_float4(0.f, 0.f, 0.f, 1e30f);
            float fdst = fsysbase + (float)j;
#pragma unroll
            for (int t = 0; t < IT; t++) {
                float d = d12_of(a[t], aj);
                bool hit = valid && (d < CUT2);
                unsigned m = __ballot_sync(0xffffffffu, hit);
                if (hit) {
                    int slot = written[t] + __popc(m & ((1u << lane) - 1u));
                    if (slot < SLOTS)
                        g_pair[((s * nat + r0 + t) * SLOTS) + slot] =
                            make_float2(fdst, d);
                }
                written[t] += __popc(m);
            }
        }

#pragma unroll
        for (int t = 0; t < IT; t++)
            if (lane == 0 && r0 + t < nat) g_counts[s * nat + r0 + t] = written[t];
    }
}

// K2: exclusive prefix scan over nrows counts (single 1024-thread block).
__global__ void scan_kernel(int nrows) {
    __shared__ int sh[1024];
    int tid = threadIdx.x;
    int per = (nrows + 1023) >> 10;
    int start = tid * per;
    int end = start + per;
    if (end > nrows) end = nrows;

    int s = 0;
    for (int k = start; k < end; k++) s += g_counts[k];
    sh[tid] = s;
    __syncthreads();

#pragma unroll
    for (int off = 1; off < 1024; off <<= 1) {
        int v = (tid >= off) ? sh[tid - off] : 0;
        __syncthreads();
        sh[tid] += v;
        __syncthreads();
    }

    int run = sh[tid] - s;
    for (int k = start; k < end; k++) {
        g_offsets[k] = run;
        run += g_counts[k];
    }
    if (tid == 1023) g_npairs = sh[1023];
}

// K3: gather stashed hits -> output buffer at scanned offsets. One warp/row.
// Output float32 layout (maxp = MAX_PAIRS):
//   [0,M): src   [M,2M): dst    (edge_src = concat(src,dst))
//   [2M,3M): dst [3M,4M): src   (edge_dst = concat(dst,src))
//   [4M,5M): d12 [5M,6M): d12   [6M]: npairs
__global__ void write_kernel(float* __restrict__ out, int maxp, int nrows) {
    int row = blockIdx.x * (blockDim.x >> 5) + (threadIdx.x >> 5);
    if (row >= nrows) return;
    int lane = threadIdx.x & 31;
    int cnt = g_counts[row];
    int off = g_offsets[row];
    float fsrc = (float)row;   // global src index == row (uniform nat)

    for (int k = lane; k < cnt && k < SLOTS; k += 32) {
        float2 p = g_pair[row * SLOTS + k];
        int pos = off + k;
        if (pos < maxp) {
            out[pos]            = fsrc;
            out[maxp + pos]     = p.x;
            out[2 * maxp + pos] = p.x;
            out[3 * maxp + pos] = fsrc;
            out[4 * maxp + pos] = p.y;
            out[5 * maxp + pos] = p.y;
        }
    }
}

// K4: padding entries (k >= npairs) + npairs scalar.
__global__ void pad_kernel(float* __restrict__ out, int maxp, float padval) {
    int k = blockIdx.x * blockDim.x + threadIdx.x;
    int np = g_npairs;
    if (k == 0) out[6 * maxp] = (float)np;
    if (k < maxp && k >= np) {
        out[k]            = padval;
        out[maxp + k]     = padval;
        out[2 * maxp + k] = padval;
        out[3 * maxp + k] = padval;
        out[4 * maxp + k] = CUT2;
        out[5 * maxp + k] = CUT2;
    }
}

extern "C" void kernel_launch(void* const* d_in, const int* in_sizes, int n_in,
                              void* d_out, int out_size) {
    const float* coords = (const float*)d_in[0];
    int n    = in_sizes[1];          // total atoms
    int nsys = in_sizes[2];          // systems
    int nat  = n / nsys;
    int maxp = (out_size - 1) / 6;   // MAX_PAIRS
    float* out = (float*)d_out;

    size_t smem = (size_t)nat * sizeof(float4);

    sweep_kernel<<<dim3(nsys, 8), 256, smem>>>(coords, nat);
    scan_kernel<<<1, 1024>>>(n);
    write_kernel<<<(n + 7) / 8, 256>>>(out, maxp, n);
    pad_kernel<<<(maxp + 255) / 256, 256>>>(out, maxp, (float)n);
}

// round 4
// speedup vs baseline: 3.0660x; 1.9494x over previous
#include <cuda_runtime.h>

#define CUT2 25.0f
#define IT 4          // i-rows per warp iteration (register tile)
#define SLOTS 128     // per-row stash capacity (mean ~26 hits)
#define NROWS_CAP 65536
#define NSYS_CAP 1024

// Scratch (static __device__, allocation-free).
__device__ int    g_counts[NROWS_CAP];
__device__ int    g_offsets[NROWS_CAP];   // within-system exclusive prefix
__device__ int    g_systot[NSYS_CAP];     // per-system totals
__device__ int    g_sysoff[NSYS_CAP];     // exclusive prefix of system totals
__device__ int    g_npairs;
__device__ float2 g_pair[NROWS_CAP * SLOTS];  // {fdst_global, d12}, j-ordered

// ---- bit-exact reference arithmetic (DO NOT CHANGE) ----
__device__ __forceinline__ float sqnorm3(float x, float y, float z) {
    return __fadd_rn(__fadd_rn(__fmul_rn(x, x), __fmul_rn(y, y)), __fmul_rn(z, z));
}
// gram dot via GEMM-style FMA chain: c = rn(x*x'); c = fma(y,y',c); c = fma(z,z',c)
__device__ __forceinline__ float dot3(float4 a, float4 b) {
    return __fmaf_rn(a.z, b.z, __fmaf_rn(a.y, b.y, __fmul_rn(a.x, b.x)));
}
__device__ __forceinline__ float d12_of(float4 ai, float4 aj) {
    return __fsub_rn(__fadd_rn(ai.w, aj.w), __fmul_rn(2.0f, dot3(ai, aj)));
}
// --------------------------------------------------------

extern __shared__ float4 s_at[];  // nat entries: (x, y, z, sq)

__device__ __forceinline__ void load_system_smem(const float* __restrict__ coords,
                                                 int s, int nat) {
    const float* base = coords + (size_t)s * nat * 3;
    for (int t = threadIdx.x; t < nat; t += blockDim.x) {
        float x = base[3 * t + 0];
        float y = base[3 * t + 1];
        float z = base[3 * t + 2];
        s_at[t] = make_float4(x, y, z, sqnorm3(x, y, z));
    }
    __syncthreads();
}

// K1: single sweep; warp handles IT consecutive rows, lanes stride j.
// Hits stashed per-row in j-order (ballot rank). grid = (nsys, G), block = 256.
__global__ void sweep_kernel(const float* __restrict__ coords, int nat) {
    int s = blockIdx.x;
    load_system_smem(coords, s, nat);

    int lane = threadIdx.x & 31;
    int wid  = (threadIdx.x >> 5) + blockIdx.y * (blockDim.x >> 5);
    int wtot = (blockDim.x >> 5) * gridDim.y;
    int ngroups = (nat + IT - 1) / IT;
    float fsysbase = (float)(s * nat);

    for (int g = wid; g < ngroups; g += wtot) {
        int r0 = g * IT;
        float4 a[IT];
        int written[IT];
#pragma unroll
        for (int t = 0; t < IT; t++) {
            int i = r0 + t;
            a[t] = (i < nat) ? s_at[i] : make_float4(0.f, 0.f, 0.f, 1e30f);
            written[t] = 0;
        }

        // Diagonal mini-block: j in (i, r0+IT), smallest j first per row.
#pragma unroll
        for (int t = 0; t < IT; t++) {
            int i = r0 + t;
            int j = i + 1 + lane;
            float d = 0.f;
            bool hit = false;
            if (j < r0 + IT && j < nat) {
                d = d12_of(a[t], s_at[j]);
                hit = (d < CUT2);
            }
            unsigned m = __ballot_sync(0xffffffffu, hit);
            if (hit) {
                int slot = __popc(m & ((1u << lane) - 1u));
                g_pair[(s * nat + i) * SLOTS + slot] =
                    make_float2(fsysbase + (float)j, d);
            }
            written[t] = __popc(m);
        }

        // Main sweep: one smem load serves IT rows.
        for (int j0 = r0 + IT; j0 < nat; j0 += 32) {
            int j = j0 + lane;
            bool valid = (j < nat);
            float4 aj = valid ? s_at[j] : make_float4(0.f, 0.f, 0.f, 1e30f);
            float fdst = fsysbase + (float)j;
#pragma unroll
            for (int t = 0; t < IT; t++) {
                float d = d12_of(a[t], aj);
                bool hit = valid && (d < CUT2);
                unsigned m = __ballot_sync(0xffffffffu, hit);
                if (hit) {
                    int slot = written[t] + __popc(m & ((1u << lane) - 1u));
                    if (slot < SLOTS)
                        g_pair[((s * nat + r0 + t) * SLOTS) + slot] =
                            make_float2(fdst, d);
                }
                written[t] += __popc(m);
            }
        }

#pragma unroll
        for (int t = 0; t < IT; t++)
            if (lane == 0 && r0 + t < nat) g_counts[s * nat + r0 + t] = written[t];
    }
}

// K2a: per-system exclusive scan (grid = nsys, block = 1024). Each thread owns
// one row. Kogge-Stone in smem. Thread nat-1 records the system total.
__global__ void scan_sys_kernel(int nat) {
    __shared__ int sh[1024];
    int s = blockIdx.x;
    int tid = threadIdx.x;
    int v = (tid < nat) ? g_counts[s * nat + tid] : 0;
    sh[tid] = v;
    __syncthreads();
#pragma unroll
    for (int off = 1; off < 1024; off <<= 1) {
        int u = (tid >= off) ? sh[tid - off] : 0;
        __syncthreads();
        sh[tid] += u;
        __syncthreads();
    }
    if (tid < nat) g_offsets[s * nat + tid] = sh[tid] - v;  // exclusive
    if (tid == nat - 1) g_systot[s] = sh[tid];
}

// K2b: top-level exclusive scan of nsys system totals (single small block).
__global__ void scan_top_kernel(int nsys) {
    __shared__ int sh[NSYS_CAP];
    int tid = threadIdx.x;
    int v = (tid < nsys) ? g_systot[tid] : 0;
    sh[tid] = v;
    __syncthreads();
    for (int off = 1; off < blockDim.x; off <<= 1) {
        int u = (tid >= off) ? sh[tid - off] : 0;
        __syncthreads();
        sh[tid] += u;
        __syncthreads();
    }
    if (tid < nsys) g_sysoff[tid] = sh[tid] - v;
    if (tid == blockDim.x - 1) g_npairs = sh[tid];
}

// K3: gather stashed hits -> output at scanned offsets. One warp per row.
// Output float32 layout (maxp = MAX_PAIRS):
//   [0,M): src   [M,2M): dst    (edge_src = concat(src,dst))
//   [2M,3M): dst [3M,4M): src   (edge_dst = concat(dst,src))
//   [4M,5M): d12 [5M,6M): d12   [6M]: npairs
__global__ void write_kernel(float* __restrict__ out, int maxp, int nrows,
                             int nat) {
    int row = blockIdx.x * (blockDim.x >> 5) + (threadIdx.x >> 5);
    if (row >= nrows) return;
    int lane = threadIdx.x & 31;
    int cnt = g_counts[row];
    int off = g_sysoff[row / nat] + g_offsets[row];
    float fsrc = (float)row;

    for (int k = lane; k < cnt && k < SLOTS; k += 32) {
        float2 p = g_pair[row * SLOTS + k];
        int pos = off + k;
        if (pos < maxp) {
            out[pos]            = fsrc;
            out[maxp + pos]     = p.x;
            out[2 * maxp + pos] = p.x;
            out[3 * maxp + pos] = fsrc;
            out[4 * maxp + pos] = p.y;
            out[5 * maxp + pos] = p.y;
        }
    }
}

// K4: padding (k >= npairs) with float4 fast path; also writes npairs scalar.
__global__ void pad_kernel(float* __restrict__ out, int maxp, float padval,
                           int vec_ok) {
    int t = blockIdx.x * blockDim.x + threadIdx.x;
    int np = g_npairs;
    if (t == 0) out[6 * maxp] = (float)np;

    int k0 = t * 4;
    if (k0 >= maxp) return;
    if (k0 + 3 < maxp && k0 >= np && vec_ok) {
        float4 pv = make_float4(padval, padval, padval, padval);
        float4 cv = make_float4(CUT2, CUT2, CUT2, CUT2);
        *(float4*)(out + k0)            = pv;
        *(float4*)(out + maxp + k0)     = pv;
        *(float4*)(out + 2 * maxp + k0) = pv;
        *(float4*)(out + 3 * maxp + k0) = pv;
        *(float4*)(out + 4 * maxp + k0) = cv;
        *(float4*)(out + 5 * maxp + k0) = cv;
    } else {
#pragma unroll
        for (int u = 0; u < 4; u++) {
            int k = k0 + u;
            if (k < maxp && k >= np) {
                out[k]            = padval;
                out[maxp + k]     = padval;
                out[2 * maxp + k] = padval;
                out[3 * maxp + k] = padval;
                out[4 * maxp + k] = CUT2;
                out[5 * maxp + k] = CUT2;
            }
        }
    }
}

extern "C" void kernel_launch(void* const* d_in, const int* in_sizes, int n_in,
                              void* d_out, int out_size) {
    const float* coords = (const float*)d_in[0];
    int n    = in_sizes[1];          // total atoms
    int nsys = in_sizes[2];          // systems
    int nat  = n / nsys;
    int maxp = (out_size - 1) / 6;   // MAX_PAIRS
    float* out = (float*)d_out;

    size_t smem = (size_t)nat * sizeof(float4);
    int topthreads = 32;
    while (topthreads < nsys) topthreads <<= 1;
    if (topthreads > NSYS_CAP) topthreads = NSYS_CAP;
    int vec_ok = ((maxp & 3) == 0) ? 1 : 0;

    sweep_kernel<<<dim3(nsys, 16), 256, smem>>>(coords, nat);
    scan_sys_kernel<<<nsys, 1024>>>(nat);
    scan_top_kernel<<<1, topthreads>>>(nsys);
    write_kernel<<<(n + 7) / 8, 256>>>(out, maxp, n, nat);
    pad_kernel<<<(maxp / 4 + 256) / 256, 256>>>(out, maxp, (float)n, vec_ok);
}

// round 5
// speedup vs baseline: 3.4312x; 1.1191x over previous
#include <cuda_runtime.h>

#define CUT2 25.0f
#define IT 4          // i-rows per warp iteration (register tile)
#define SLOTS 128     // per-row stash capacity (mean ~26 hits)
#define NROWS_CAP 65536
#define NSYS_CAP 2048

// Scratch (static __device__, allocation-free).
__device__ int    g_counts[NROWS_CAP];
__device__ int    g_offsets[NROWS_CAP];   // within-system exclusive prefix
__device__ int    g_systot[NSYS_CAP];     // per-system totals
__device__ float2 g_pair[NROWS_CAP * SLOTS];  // {fdst_global, d12}, j-ordered

// ---- bit-exact reference arithmetic (DO NOT CHANGE) ----
__device__ __forceinline__ float sqnorm3(float x, float y, float z) {
    return __fadd_rn(__fadd_rn(__fmul_rn(x, x), __fmul_rn(y, y)), __fmul_rn(z, z));
}
// gram dot via GEMM-style FMA chain: c = rn(x*x'); c = fma(y,y',c); c = fma(z,z',c)
__device__ __forceinline__ float dot3(float4 a, float4 b) {
    return __fmaf_rn(a.z, b.z, __fmaf_rn(a.y, b.y, __fmul_rn(a.x, b.x)));
}
__device__ __forceinline__ float d12_of(float4 ai, float4 aj) {
    return __fsub_rn(__fadd_rn(ai.w, aj.w), __fmul_rn(2.0f, dot3(ai, aj)));
}
// --------------------------------------------------------

extern __shared__ float4 s_at[];  // nat + 35 entries: (x, y, z, sq); tail = sentinel

// K1: single sweep; warp handles IT consecutive rows, lanes stride j.
// smem is sentinel-padded so the j-loop needs no bounds predication.
__global__ void sweep_kernel(const float* __restrict__ coords, int nat) {
    int s = blockIdx.x;
    {
        const float* base = coords + (size_t)s * nat * 3;
        int P = nat + 35;
        for (int t = threadIdx.x; t < P; t += blockDim.x) {
            if (t < nat) {
                float x = base[3 * t + 0];
                float y = base[3 * t + 1];
                float z = base[3 * t + 2];
                s_at[t] = make_float4(x, y, z, sqnorm3(x, y, z));
            } else {
                s_at[t] = make_float4(0.f, 0.f, 0.f, 1e30f);  // never within cutoff
            }
        }
        __syncthreads();
    }

    int lane = threadIdx.x & 31;
    unsigned lm = (1u << lane) - 1u;
    int wid  = (threadIdx.x >> 5) + blockIdx.y * (blockDim.x >> 5);
    int wtot = (blockDim.x >> 5) * gridDim.y;
    int ngroups = (nat + IT - 1) / IT;
    float fsysbase = (float)(s * nat);

    for (int g = wid; g < ngroups; g += wtot) {
        int r0 = g * IT;
        float4 a[IT];
        int written[IT];
        float2* bp[IT];
#pragma unroll
        for (int t = 0; t < IT; t++) {
            int i = r0 + t;
            a[t] = (i < nat) ? s_at[i] : make_float4(0.f, 0.f, 0.f, 1e30f);
            written[t] = 0;
            bp[t] = &g_pair[(size_t)(s * nat + i) * SLOTS];
        }

        // Diagonal mini-block: j in (i, r0+IT), smallest j first per row.
#pragma unroll
        for (int t = 0; t < IT - 1; t++) {
            int i = r0 + t;
            int j = i + 1 + lane;
            float d = 1e30f;
            if (j < r0 + IT && j < nat) d = d12_of(a[t], s_at[j]);
            bool hit = (d < CUT2);
            unsigned m = __ballot_sync(0xffffffffu, hit);
            int slot = __popc(m & lm);
            if (hit) bp[t][slot] = make_float2(fsysbase + (float)j, d);
            written[t] = __popc(m);
        }

        // Main sweep: one smem load serves IT rows; no bounds checks (sentinels).
        for (int j0 = r0 + IT; j0 < nat; j0 += 32) {
            int j = j0 + lane;
            float4 aj = s_at[j];
            float fdst = fsysbase + (float)j;
#pragma unroll
            for (int t = 0; t < IT; t++) {
                float d = d12_of(a[t], aj);
                bool hit = (d < CUT2);
                unsigned m = __ballot_sync(0xffffffffu, hit);
                int slot = written[t] + __popc(m & lm);
                if (hit && slot < SLOTS) bp[t][slot] = make_float2(fdst, d);
                written[t] += __popc(m);
            }
        }

#pragma unroll
        for (int t = 0; t < IT; t++)
            if (lane == 0 && r0 + t < nat) g_counts[s * nat + r0 + t] = written[t];
    }
}

// K2: per-system exclusive scan via shfl warp-scan + cross-warp pass.
// grid = nsys, block = 1024 (requires nat <= 1024).
__global__ void scan_sys_kernel(int nat) {
    __shared__ int wsum[32];
    int s = blockIdx.x;
    int tid = threadIdx.x;
    int lane = tid & 31, w = tid >> 5;
    int v = (tid < nat) ? g_counts[s * nat + tid] : 0;

    int x = v;  // inclusive scan within warp
#pragma unroll
    for (int o = 1; o < 32; o <<= 1) {
        int u = __shfl_up_sync(0xffffffffu, x, o);
        if (lane >= o) x += u;
    }
    if (lane == 31) wsum[w] = x;
    __syncthreads();
    if (w == 0) {
        int y = wsum[lane];
#pragma unroll
        for (int o = 1; o < 32; o <<= 1) {
            int u = __shfl_up_sync(0xffffffffu, y, o);
            if (lane >= o) y += u;
        }
        wsum[lane] = y;  // inclusive warp totals
    }
    __syncthreads();
    int incl = x + ((w > 0) ? wsum[w - 1] : 0);
    if (tid < nat) g_offsets[s * nat + tid] = incl - v;
    if (tid == nat - 1) g_systot[s] = incl;
}

// K3: fused output kernel. Blocks [0, WB) write compacted hits; blocks
// [WB, gridDim.x) write the padding region — concurrent, disjoint ranges.
// Every block derives the system-offset prefix from g_systot with one
// warp-shfl scan (nsys <= 64: two entries per lane).
// Output float32 layout (maxp = MAX_PAIRS):
//   [0,M): src   [M,2M): dst    (edge_src = concat(src,dst))
//   [2M,3M): dst [3M,4M): src   (edge_dst = concat(dst,src))
//   [4M,5M): d12 [5M,6M): d12   [6M]: npairs
__global__ void output_kernel(float* __restrict__ out, int maxp, int nrows,
                              int nat, int nsys, int WB, float padval,
                              int vec_ok) {
    __shared__ int s_sysoff[NSYS_CAP + 1];  // exclusive offsets; [nsys] = total
    int tid = threadIdx.x;
    if (tid < 32) {
        int per = (nsys + 31) >> 5;  // entries per lane (consecutive)
        int base = tid * per;
        int loc[64 / 32 + 2];  // enough for nsys<=64 (per<=2); generic small
        int sum = 0;
        for (int u = 0; u < per; u++) {
            int idx = base + u;
            int t = (idx < nsys) ? g_systot[idx] : 0;
            loc[u] = sum;  // local exclusive
            sum += t;
        }
        int x = sum;  // inclusive scan of lane sums
#pragma unroll
        for (int o = 1; o < 32; o <<= 1) {
            int uu = __shfl_up_sync(0xffffffffu, x, o);
            if ((tid & 31) >= o) x += uu;
        }
        int excl = x - sum;
        for (int u = 0; u < per; u++) {
            int idx = base + u;
            if (idx <= nsys) s_sysoff[idx] = excl + loc[u];
        }
        if (tid == 31) s_sysoff[nsys] = x;  // grand total = npairs
    }
    __syncthreads();
    int np = s_sysoff[nsys];

    if (blockIdx.x < WB) {
        // ---- write duty: one warp per row ----
        int row = blockIdx.x * (blockDim.x >> 5) + (tid >> 5);
        if (row >= nrows) return;
        int lane = tid & 31;
        int cnt = g_counts[row];
        int off = s_sysoff[row / nat] + g_offsets[row];
        float fsrc = (float)row;

        for (int k = lane; k < cnt && k < SLOTS; k += 32) {
            float2 p = g_pair[(size_t)row * SLOTS + k];
            int pos = off + k;
            if (pos < maxp) {
                out[pos]            = fsrc;
                out[maxp + pos]     = p.x;
                out[2 * maxp + pos] = p.x;
                out[3 * maxp + pos] = fsrc;
                out[4 * maxp + pos] = p.y;
                out[5 * maxp + pos] = p.y;
            }
        }
    } else {
        // ---- pad duty: k in [np, maxp), float4 fast path ----
        int pb = blockIdx.x - WB;
        if (pb == 0 && tid == 0) out[6 * maxp] = (float)np;
        int k0 = (pb * blockDim.x + tid) * 4;
        if (k0 >= maxp) return;
        if (k0 >= np && k0 + 3 < maxp && vec_ok) {
            float4 pv = make_float4(padval, padval, padval, padval);
            float4 cv = make_float4(CUT2, CUT2, CUT2, CUT2);
            *(float4*)(out + k0)            = pv;
            *(float4*)(out + maxp + k0)     = pv;
            *(float4*)(out + 2 * maxp + k0) = pv;
            *(float4*)(out + 3 * maxp + k0) = pv;
            *(float4*)(out + 4 * maxp + k0) = cv;
            *(float4*)(out + 5 * maxp + k0) = cv;
        } else {
#pragma unroll
            for (int u = 0; u < 4; u++) {
                int k = k0 + u;
                if (k < maxp && k >= np) {
                    out[k]            = padval;
                    out[maxp + k]     = padval;
                    out[2 * maxp + k] = padval;
                    out[3 * maxp + k] = padval;
                    out[4 * maxp + k] = CUT2;
                    out[5 * maxp + k] = CUT2;
                }
            }
        }
    }
}

extern "C" void kernel_launch(void* const* d_in, const int* in_sizes, int n_in,
                              void* d_out, int out_size) {
    const float* coords = (const float*)d_in[0];
    int n    = in_sizes[1];          // total atoms
    int nsys = in_sizes[2];          // systems
    int nat  = n / nsys;
    int maxp = (out_size - 1) / 6;   // MAX_PAIRS
    float* out = (float*)d_out;

    size_t smem = (size_t)(nat + 35) * sizeof(float4);
    int vec_ok = ((maxp & 3) == 0) ? 1 : 0;

    int warps_per_block = 8;
    int WB = (n + warps_per_block - 1) / warps_per_block;    // write blocks
    int PB = (maxp + 256 * 4 - 1) / (256 * 4);               // pad blocks

    sweep_kernel<<<dim3(nsys, 16), 256, smem>>>(coords, nat);
    scan_sys_kernel<<<nsys, 1024>>>(nat);
    output_kernel<<<WB + PB, 256>>>(out, maxp, n, nat, nsys, WB, (float)n,
                                    vec_ok);
}